// round 1
// baseline (speedup 1.0000x reference)
#include <cuda_runtime.h>
#include <math.h>

// ---------------- problem constants ----------------
#define D_NODE 100
#define D_HID  300
#define NB     128          // batch
#define NT     512          // triples per batch
#define NNODE  256          // nodes per batch
#define NLQ    256          // query length
#define ROWS_BT (NB*NT)     // 65536
#define ROWS_BN (NB*NNODE)  // 32768

// output layout (float32): path_feature[128*300] | node_feature[128*256*300] | mask zeros
#define OUT_PATH   (NB*D_HID)                 // 38400
#define OUT_NODEF  ((long)ROWS_BN*D_HID)      // 9830400
#define OUT_TAIL_START (OUT_PATH + OUT_NODEF) // 9868800

// ---------------- device scratch (static; no allocs) ----------------
__device__ float g_Wc[1800 * D_NODE];              // combined GRU-input weights (f then b)
__device__ float g_c[1800];                        // combined biases (b_hh folded for r,z)
__device__ float g_U[(size_t)ROWS_BN * 1800];      // per-node gate pre-activations  (~236MB)
__device__ float g_hidden[(size_t)ROWS_BT * 600];  // [h_f, h_b]                      (~157MB)
__device__ float g_hid[(size_t)ROWS_BT * D_HID];   // tanh(hidden@W_out^T)            (~79MB)
__device__ float g_scores[(size_t)NB * NLQ * NT];  //                                 (~67MB)
__device__ float g_alpha[NB * NT];

// ---------------- generic SGEMM: C[m,n] = act( sum_k A[m,k]*W[n,k] + bias[n] ) ----------------
// A: [M,K] row-major (lda=K). W: [N,K] row-major. C: [M,N] row-major (ldc=N).
// M must be a multiple of 128 (true for all call sites). K must be a multiple of 4.
#define GM 128
#define GN 128
#define GK 16

__global__ void __launch_bounds__(256)
sgemm_nt(const float* __restrict__ A, long aBatch,
         const float* __restrict__ W, long wBatch,
         float* __restrict__ C, long cBatch,
         int M, int N, int K,
         const float* __restrict__ bias, int act_tanh)
{
    const int bz = blockIdx.z;
    A += (long)bz * aBatch;
    W += (long)bz * wBatch;
    C += (long)bz * cBatch;

    const int m0 = blockIdx.y * GM;
    const int n0 = blockIdx.x * GN;

    __shared__ __align__(16) float As[GK][GM + 4];
    __shared__ __align__(16) float Bs[GK][GN + 4];

    const int tid = threadIdx.x;
    const int tx = tid & 15;       // n direction
    const int ty = tid >> 4;       // m direction
    const int lr = tid >> 2;       // loader row 0..63
    const int lc = (tid & 3) * 4;  // loader k-chunk 0,4,8,12

    float acc[8][8];
#pragma unroll
    for (int i = 0; i < 8; ++i)
#pragma unroll
        for (int j = 0; j < 8; ++j) acc[i][j] = 0.f;

    for (int k0 = 0; k0 < K; k0 += GK) {
        // load A tile (rows always valid: M % 128 == 0 at all call sites)
#pragma unroll
        for (int h = 0; h < 2; ++h) {
            const int m = m0 + lr + h * 64;
            float4 v = make_float4(0.f, 0.f, 0.f, 0.f);
            if (k0 + lc < K)  // K%4==0 -> chunk fully in-range or fully out
                v = *reinterpret_cast<const float4*>(A + (long)m * K + k0 + lc);
            As[lc + 0][lr + h * 64] = v.x;
            As[lc + 1][lr + h * 64] = v.y;
            As[lc + 2][lr + h * 64] = v.z;
            As[lc + 3][lr + h * 64] = v.w;
        }
        // load W tile
#pragma unroll
        for (int h = 0; h < 2; ++h) {
            const int n = n0 + lr + h * 64;
            float4 v = make_float4(0.f, 0.f, 0.f, 0.f);
            if (n < N && (k0 + lc < K))
                v = *reinterpret_cast<const float4*>(W + (long)n * K + k0 + lc);
            Bs[lc + 0][lr + h * 64] = v.x;
            Bs[lc + 1][lr + h * 64] = v.y;
            Bs[lc + 2][lr + h * 64] = v.z;
            Bs[lc + 3][lr + h * 64] = v.w;
        }
        __syncthreads();

#pragma unroll
        for (int kk = 0; kk < GK; ++kk) {
            float a[8], b[8];
#pragma unroll
            for (int i = 0; i < 8; ++i) a[i] = As[kk][ty * 8 + i];
#pragma unroll
            for (int j = 0; j < 8; ++j) b[j] = Bs[kk][tx * 8 + j];
#pragma unroll
            for (int i = 0; i < 8; ++i)
#pragma unroll
                for (int j = 0; j < 8; ++j)
                    acc[i][j] = fmaf(a[i], b[j], acc[i][j]);
        }
        __syncthreads();
    }

#pragma unroll
    for (int i = 0; i < 8; ++i) {
        const int m = m0 + ty * 8 + i;
#pragma unroll
        for (int j = 0; j < 8; ++j) {
            const int n = n0 + tx * 8 + j;
            if (n < N) {
                float v = acc[i][j];
                if (bias) v += bias[n];
                if (act_tanh) v = tanhf(v);
                C[(long)m * N + n] = v;
            }
        }
    }
}

// ---------------- weight combine: Wc = W_ih @ W_mean ; c = W_ih@b_mean + b_ih (+b_hh for r,z) ---
__global__ void combine_kernel(const float* __restrict__ Wf, const float* __restrict__ bif,
                               const float* __restrict__ bhf,
                               const float* __restrict__ Wb, const float* __restrict__ bib,
                               const float* __restrict__ bhb,
                               const float* __restrict__ Wmean, const float* __restrict__ bmean)
{
    const int j = blockIdx.x;                 // 0..1799
    const int fwd = (j < 900);
    const int jj = fwd ? j : j - 900;
    const float* Wih = fwd ? Wf : Wb;

    __shared__ float wrow[D_HID];
    for (int d = threadIdx.x; d < D_HID; d += blockDim.x)
        wrow[d] = Wih[jj * D_HID + d];
    __syncthreads();

    for (int k = threadIdx.x; k < D_NODE; k += blockDim.x) {
        float s = 0.f;
        for (int d = 0; d < D_HID; ++d)
            s = fmaf(wrow[d], Wmean[d * D_NODE + k], s);
        g_Wc[j * D_NODE + k] = s;
    }
    if (threadIdx.x == 0) {
        const float* bih = fwd ? bif : bib;
        const float* bhh = fwd ? bhf : bhb;
        float s = bih[jj];
        for (int d = 0; d < D_HID; ++d) s = fmaf(wrow[d], bmean[d], s);
        if (jj < 600) s += bhh[jj];           // fold b_hh into r,z gates
        g_c[j] = s;
    }
}

// ---------------- GRU gates: gi = 0.5*(u[head]+u[tail]) (bias already in u) -------------------
__global__ void gates_kernel(const int* __restrict__ triples,
                             const float* __restrict__ bhf,
                             const float* __restrict__ bhb)
{
    const int bt = blockIdx.x;                // 0..65535
    const int b = bt >> 9;                    // /512
    const int h = triples[bt * 3 + 0];
    const int t = triples[bt * 3 + 2];
    const float* uh = g_U + (size_t)(b * NNODE + h) * 1800;
    const float* ut = g_U + (size_t)(b * NNODE + t) * 1800;
    float* out = g_hidden + (size_t)bt * 600;

    for (int j = threadIdx.x; j < D_HID; j += blockDim.x) {
        // forward direction (cols 0..899)
        float r = 0.5f * (uh[j] + ut[j]);
        float z = 0.5f * (uh[300 + j] + ut[300 + j]);
        float n = 0.5f * (uh[600 + j] + ut[600 + j]);
        r = 1.f / (1.f + expf(-r));
        z = 1.f / (1.f + expf(-z));
        n = tanhf(n + r * bhf[600 + j]);
        out[j] = (1.f - z) * n;
        // backward direction (cols 900..1799)
        float r2 = 0.5f * (uh[900 + j] + ut[900 + j]);
        float z2 = 0.5f * (uh[1200 + j] + ut[1200 + j]);
        float n2 = 0.5f * (uh[1500 + j] + ut[1500 + j]);
        r2 = 1.f / (1.f + expf(-r2));
        z2 = 1.f / (1.f + expf(-z2));
        n2 = tanhf(n2 + r2 * bhb[600 + j]);
        out[300 + j] = (1.f - z2) * n2;
    }
}

// ---------------- softmax over t per (b,l), then alpha[b,t] = sum_l ---------------------------
__global__ void __launch_bounds__(512) softmax_alpha_kernel()
{
    const int b = blockIdx.x;
    const float* S = g_scores + (size_t)b * NLQ * NT;
    __shared__ float rmax[NLQ];
    __shared__ float rinv[NLQ];

    const int tid = threadIdx.x;              // 512
    const int wid = tid >> 5, lane = tid & 31;

    // phase 1: per-row max and 1/sum (warp per row)
    for (int l = wid; l < NLQ; l += 16) {
        const float* row = S + (size_t)l * NT;
        float v[16], m = -1e30f;
#pragma unroll
        for (int q = 0; q < 16; ++q) { v[q] = row[lane + 32 * q]; m = fmaxf(m, v[q]); }
#pragma unroll
        for (int o = 16; o; o >>= 1) m = fmaxf(m, __shfl_xor_sync(0xffffffffu, m, o));
        float s = 0.f;
#pragma unroll
        for (int q = 0; q < 16; ++q) s += expf(v[q] - m);
#pragma unroll
        for (int o = 16; o; o >>= 1) s += __shfl_xor_sync(0xffffffffu, s, o);
        if (lane == 0) { rmax[l] = m; rinv[l] = 1.f / s; }
    }
    __syncthreads();

    // phase 2: deterministic column accumulation
    float acc = 0.f;
    const int t = tid;
    for (int l = 0; l < NLQ; ++l)
        acc += expf(S[(size_t)l * NT + t] - rmax[l]) * rinv[l];
    g_alpha[b * NT + t] = acc;
}

// ---------------- rep = alpha @ hid_ ; layernorm -> path_feature ------------------------------
__global__ void __launch_bounds__(320) rep_ln_kernel(const float* __restrict__ gamma,
                                                     const float* __restrict__ beta,
                                                     float* __restrict__ out)
{
    const int b = blockIdx.x;
    __shared__ float sal[NT];
    __shared__ float red[2][10];
    const int tid = threadIdx.x;              // 320

    for (int t = tid; t < NT; t += 320) sal[t] = g_alpha[b * NT + t];
    __syncthreads();

    float acc = 0.f;
    const float* H = g_hid + (size_t)b * NT * D_HID;
    if (tid < D_HID) {
        for (int t = 0; t < NT; ++t)
            acc = fmaf(sal[t], H[(size_t)t * D_HID + tid], acc);
    }
    float v1 = (tid < D_HID) ? acc : 0.f;
    float v2 = (tid < D_HID) ? acc * acc : 0.f;
#pragma unroll
    for (int o = 16; o; o >>= 1) {
        v1 += __shfl_xor_sync(0xffffffffu, v1, o);
        v2 += __shfl_xor_sync(0xffffffffu, v2, o);
    }
    const int wid = tid >> 5, lane = tid & 31;
    if (lane == 0) { red[0][wid] = v1; red[1][wid] = v2; }
    __syncthreads();
    if (tid == 0) {
        float s1 = 0.f, s2 = 0.f;
        for (int w = 0; w < 10; ++w) { s1 += red[0][w]; s2 += red[1][w]; }
        red[0][0] = s1 / (float)D_HID;
        red[1][0] = s2 / (float)D_HID;
    }
    __syncthreads();
    if (tid < D_HID) {
        float mu = red[0][0];
        float var = red[1][0] - mu * mu;
        out[b * D_HID + tid] = (acc - mu) * rsqrtf(var + 1e-5f) * gamma[tid] + beta[tid];
    }
}

// ---------------- zero the node_mask tail of the output ---------------------------------------
__global__ void zero_tail_kernel(float* __restrict__ out, long start, long end)
{
    long i = start + (long)blockIdx.x * blockDim.x + threadIdx.x;
    if (i < end) out[i] = 0.f;
}

// ---------------- launch ----------------------------------------------------------------------
extern "C" void kernel_launch(void* const* d_in, const int* in_sizes, int n_in,
                              void* d_out, int out_size)
{
    // node_number may or may not appear as a (size-1) input between dia_triples and W_mean
    const int o = (in_sizes[3] == 1) ? 1 : 0;

    const float* nodes  = (const float*)d_in[0];
    const float* ctx    = (const float*)d_in[1];
    const int*   tri    = (const int*)d_in[2];
    const float* W_mean = (const float*)d_in[3 + o];
    const float* b_mean = (const float*)d_in[4 + o];
    const float* W_ih_f = (const float*)d_in[5 + o];
    const float* b_ih_f = (const float*)d_in[6 + o];
    const float* b_hh_f = (const float*)d_in[7 + o];
    const float* W_ih_b = (const float*)d_in[8 + o];
    const float* b_ih_b = (const float*)d_in[9 + o];
    const float* b_hh_b = (const float*)d_in[10 + o];
    const float* W_out  = (const float*)d_in[11 + o];
    const float* b_out  = (const float*)d_in[12 + o];
    const float* W_node = (const float*)d_in[13 + o];
    const float* b_node = (const float*)d_in[14 + o];
    const float* gamma  = (const float*)d_in[15 + o];
    const float* beta   = (const float*)d_in[16 + o];
    float* out = (float*)d_out;

    float *pWc, *pC, *pU, *pHidden, *pHid, *pScores;
    cudaGetSymbolAddress((void**)&pWc,     g_Wc);
    cudaGetSymbolAddress((void**)&pC,      g_c);
    cudaGetSymbolAddress((void**)&pU,      g_U);
    cudaGetSymbolAddress((void**)&pHidden, g_hidden);
    cudaGetSymbolAddress((void**)&pHid,    g_hid);
    cudaGetSymbolAddress((void**)&pScores, g_scores);

    // 1. combined weights/biases
    combine_kernel<<<1800, 128>>>(W_ih_f, b_ih_f, b_hh_f, W_ih_b, b_ih_b, b_hh_b, W_mean, b_mean);

    // 2. per-node gate pre-activations: U[32768,1800] = nodes @ Wc^T + c
    {
        dim3 grid((1800 + GN - 1) / GN, ROWS_BN / GM, 1);
        sgemm_nt<<<grid, 256>>>(nodes, 0, pWc, 0, pU, 0, ROWS_BN, 1800, D_NODE, pC, 0);
    }

    // 3. node_feature -> d_out[38400 ...]: [32768,300] = nodes @ W_node^T + b_node
    {
        dim3 grid((D_HID + GN - 1) / GN, ROWS_BN / GM, 1);
        sgemm_nt<<<grid, 256>>>(nodes, 0, W_node, 0, out + OUT_PATH, 0,
                                ROWS_BN, D_HID, D_NODE, b_node, 0);
    }

    // 4. GRU gates -> hidden[65536,600]
    gates_kernel<<<ROWS_BT, 256>>>(tri, b_hh_f, b_hh_b);

    // 5. hid_[65536,300] = tanh(hidden @ W_out^T + b_out)
    {
        dim3 grid((D_HID + GN - 1) / GN, ROWS_BT / GM, 1);
        sgemm_nt<<<grid, 256>>>(pHidden, 0, W_out, 0, pHid, 0, ROWS_BT, D_HID, 600, b_out, 1);
    }

    // 6. scores[b,256,512] = ctx[b] @ hid_[b]^T  (batched)
    {
        dim3 grid((NT + GN - 1) / GN, NLQ / GM, NB);
        sgemm_nt<<<grid, 256>>>(ctx, (long)NLQ * D_HID,
                                pHid, (long)NT * D_HID,
                                pScores, (long)NLQ * NT,
                                NLQ, NT, D_HID, nullptr, 0);
    }

    // 7. softmax over t, sum over l -> alpha[b,t]
    softmax_alpha_kernel<<<NB, 512>>>();

    // 8. rep + layernorm -> path_feature (d_out[0:38400])
    rep_ln_kernel<<<NB, 320>>>(gamma, beta, out);

    // 9. node_mask region (all False -> zeros) and any remaining tail
    {
        long start = OUT_TAIL_START;
        long end = (long)out_size;
        if (end > start) {
            long n = end - start;
            int blocks = (int)((n + 255) / 256);
            zero_tail_kernel<<<blocks, 256>>>(out, start, end);
        }
    }
}

// round 3
// speedup vs baseline: 2.6982x; 2.6982x over previous
#include <cuda_runtime.h>
#include <math.h>
#include <stdint.h>

// ---------------- problem constants ----------------
#define D_NODE 100
#define D_HID  300
#define NB     128
#define NT     512
#define NNODE  256
#define NLQ    256
#define ROWS_BT (NB*NT)     // 65536
#define ROWS_BN (NB*NNODE)  // 32768

#define OUT_PATH   (NB*D_HID)
#define OUT_NODEF  ((long)ROWS_BN*D_HID)
#define OUT_TAIL_START (OUT_PATH + OUT_NODEF)

// ---------------- device scratch ----------------
__device__ float g_Wc[1800 * D_NODE];
__device__ float g_c[1800];
__device__ float g_U[(size_t)ROWS_BN * 1800];
__device__ float g_hidden[(size_t)ROWS_BT * 600];
__device__ float g_hid[(size_t)ROWS_BT * D_HID];
__device__ float g_scores[(size_t)NB * NLQ * NT];
__device__ float g_alpha[NB * NT];

// ---------------- PTX helpers (plain sm_10x — NO tcgen05) ----------------
__device__ __forceinline__ uint32_t smem_to_u32(const void* p) {
    uint32_t a;
    asm("{ .reg .u64 t; cvta.to.shared.u64 t, %1; cvt.u32.u64 %0, t; }" : "=r"(a) : "l"(p));
    return a;
}
__device__ __forceinline__ uint32_t f2tf32(float f) {
    uint32_t u;
    asm("cvt.rna.tf32.f32 %0, %1;" : "=r"(u) : "f"(f));
    return u;
}
__device__ __forceinline__ void mma_tf32(float* d, const uint32_t* a, const uint32_t* b) {
    asm volatile(
        "mma.sync.aligned.m16n8k8.row.col.f32.tf32.tf32.f32 "
        "{%0,%1,%2,%3}, {%4,%5,%6,%7}, {%8,%9}, {%0,%1,%2,%3};"
        : "+f"(d[0]), "+f"(d[1]), "+f"(d[2]), "+f"(d[3])
        : "r"(a[0]), "r"(a[1]), "r"(a[2]), "r"(a[3]), "r"(b[0]), "r"(b[1]));
}
__device__ __forceinline__ void cp_async16(uint32_t dst, const void* src, int src_size) {
    asm volatile("cp.async.cg.shared.global [%0], [%1], 16, %2;"
        :: "r"(dst), "l"(src), "r"(src_size) : "memory");
}
#define CP_COMMIT() asm volatile("cp.async.commit_group;" ::: "memory")
#define CP_WAIT(n)  asm volatile("cp.async.wait_group %0;" :: "n"(n) : "memory")

// ================= tf32 mma.sync GEMM =================
// C[m,n] = act( sum_k A[m,k]*W[n,k] + bias[n] ). A:[M,K] rm, W:[N,K] rm, C:[M,N] rm.
// M % 128 == 0 at all call sites; K % 4 == 0; N even.
#define BM 128
#define BN 128
#define SSTR 36                      // smem row stride in floats (conflict-free for frags)
#define TILE_FLOATS (128 * SSTR)     // one operand tile
#define BUF_FLOATS  (2 * TILE_FLOATS)
#define GEMM_SMEM_BYTES (2 * BUF_FLOATS * 4)   // 73728

__global__ void __launch_bounds__(256, 2)
gemm_tf32_mma(const float* __restrict__ A, long aBatch,
              const float* __restrict__ W, long wBatch,
              float* __restrict__ C, long cBatch,
              int M, int N, int K,
              const float* __restrict__ bias, int act_tanh)
{
    extern __shared__ float sm[];
    const uint32_t smem_base = smem_to_u32(sm);

    const int bz = blockIdx.z;
    A += (long)bz * aBatch; W += (long)bz * wBatch; C += (long)bz * cBatch;

    const int tid  = threadIdx.x;
    const int warp = tid >> 5, lane = tid & 31;
    const int wm = warp & 3, wn = warp >> 2;      // 4 x 2 warp grid
    const int g = lane >> 2, t = lane & 3;

    const int m0 = blockIdx.y * BM;
    const int n0 = blockIdx.x * BN;
    const int CH = (K + 31) >> 5;

    float acc[2][8][4];
#pragma unroll
    for (int i = 0; i < 2; ++i)
#pragma unroll
        for (int j = 0; j < 8; ++j)
#pragma unroll
            for (int q = 0; q < 4; ++q) acc[i][j][q] = 0.f;

    // issue cp.async loads for chunk c into buffer c&1
    auto issue = [&](int c) {
        const int s = c & 1;
        const int kb = c << 5;
        const uint32_t aBase = smem_base + (uint32_t)(s * BUF_FLOATS) * 4u;
        const uint32_t bBase = aBase + (uint32_t)TILE_FLOATS * 4u;
#pragma unroll
        for (int i = 0; i < 4; ++i) {
            const int seg = tid + i * 256;         // 0..1023
            const int row = seg >> 3;
            const int q   = seg & 7;
            const int k   = kb + q * 4;
            const int va  = (k + 4 <= K);
            cp_async16(aBase + (uint32_t)(row * SSTR + q * 4) * 4u,
                       va ? (A + (long)(m0 + row) * K + k) : A, va ? 16 : 0);
            const int vb  = va && (n0 + row < N);
            cp_async16(bBase + (uint32_t)(row * SSTR + q * 4) * 4u,
                       vb ? (W + (long)(n0 + row) * K + k) : W, vb ? 16 : 0);
        }
        CP_COMMIT();
    };

    issue(0);
    for (int c = 0; c < CH; ++c) {
        if (c + 1 < CH) { issue(c + 1); CP_WAIT(1); }
        else            { CP_WAIT(0); }
        __syncthreads();

        const float* a_ = sm + (c & 1) * BUF_FLOATS;
        const float* b_ = a_ + TILE_FLOATS;

#pragma unroll
        for (int kk = 0; kk < 4; ++kk) {
            const int col = kk * 8 + t;
            uint32_t af[2][4], bf[8][2];
#pragma unroll
            for (int tm = 0; tm < 2; ++tm) {
                const int r = wm * 32 + tm * 16 + g;
                af[tm][0] = f2tf32(a_[r * SSTR + col]);
                af[tm][1] = f2tf32(a_[(r + 8) * SSTR + col]);
                af[tm][2] = f2tf32(a_[r * SSTR + col + 4]);
                af[tm][3] = f2tf32(a_[(r + 8) * SSTR + col + 4]);
            }
#pragma unroll
            for (int tn = 0; tn < 8; ++tn) {
                const int n = wn * 64 + tn * 8 + g;
                bf[tn][0] = f2tf32(b_[n * SSTR + col]);
                bf[tn][1] = f2tf32(b_[n * SSTR + col + 4]);
            }
#pragma unroll
            for (int tm = 0; tm < 2; ++tm)
#pragma unroll
                for (int tn = 0; tn < 8; ++tn)
                    mma_tf32(acc[tm][tn], af[tm], bf[tn]);
        }
        __syncthreads();
    }

    // epilogue: rows (wm*32+tm*16+g, +8), cols (wn*64+tn*8+2t, +1)
#pragma unroll
    for (int tm = 0; tm < 2; ++tm) {
        const int row = m0 + wm * 32 + tm * 16 + g;
#pragma unroll
        for (int tn = 0; tn < 8; ++tn) {
            const int n = n0 + wn * 64 + tn * 8 + 2 * t;
            if (n < N) {   // N even -> pair never splits
                float b0 = 0.f, b1 = 0.f;
                if (bias) { b0 = bias[n]; b1 = bias[n + 1]; }
                float v0 = acc[tm][tn][0] + b0;
                float v1 = acc[tm][tn][1] + b1;
                float v2 = acc[tm][tn][2] + b0;
                float v3 = acc[tm][tn][3] + b1;
                if (act_tanh) { v0 = tanhf(v0); v1 = tanhf(v1); v2 = tanhf(v2); v3 = tanhf(v3); }
                *(float2*)(C + (long)row * N + n)       = make_float2(v0, v1);
                *(float2*)(C + (long)(row + 8) * N + n) = make_float2(v2, v3);
            }
        }
    }
}

// ---------------- weight combine ----------------
__global__ void combine_kernel(const float* __restrict__ Wf, const float* __restrict__ bif,
                               const float* __restrict__ bhf,
                               const float* __restrict__ Wb, const float* __restrict__ bib,
                               const float* __restrict__ bhb,
                               const float* __restrict__ Wmean, const float* __restrict__ bmean)
{
    const int j = blockIdx.x;
    const int fwd = (j < 900);
    const int jj = fwd ? j : j - 900;
    const float* Wih = fwd ? Wf : Wb;

    __shared__ float wrow[D_HID];
    for (int d = threadIdx.x; d < D_HID; d += blockDim.x)
        wrow[d] = Wih[jj * D_HID + d];
    __syncthreads();

    for (int k = threadIdx.x; k < D_NODE; k += blockDim.x) {
        float s = 0.f;
        for (int d = 0; d < D_HID; ++d)
            s = fmaf(wrow[d], Wmean[d * D_NODE + k], s);
        g_Wc[j * D_NODE + k] = s;
    }
    if (threadIdx.x == 0) {
        const float* bih = fwd ? bif : bib;
        const float* bhh = fwd ? bhf : bhb;
        float s = bih[jj];
        for (int d = 0; d < D_HID; ++d) s = fmaf(wrow[d], bmean[d], s);
        if (jj < 600) s += bhh[jj];
        g_c[j] = s;
    }
}

// ---------------- GRU gates (float4 vectorized) ----------------
__device__ __forceinline__ float4 avg4(float4 a, float4 b) {
    return make_float4(0.5f * (a.x + b.x), 0.5f * (a.y + b.y),
                       0.5f * (a.z + b.z), 0.5f * (a.w + b.w));
}
__global__ void __launch_bounds__(160) gates_kernel(const int* __restrict__ tri,
                                                    const float* __restrict__ bhf,
                                                    const float* __restrict__ bhb)
{
    const int bt = blockIdx.x;
    const int b = bt >> 9;
    const int h = tri[bt * 3 + 0];
    const int t = tri[bt * 3 + 2];
    const float4* uh = (const float4*)(g_U + (size_t)(b * NNODE + h) * 1800);
    const float4* ut = (const float4*)(g_U + (size_t)(b * NNODE + t) * 1800);
    float4* out = (float4*)(g_hidden + (size_t)bt * 600);

    const int tid = threadIdx.x;
    int grp, j;
    if (tid < 75)                    { grp = 0; j = tid; }
    else if (tid >= 80 && tid < 155) { grp = 1; j = tid - 80; }
    else return;

    const int base = grp * 225;
    const float* bh = grp ? bhb : bhf;
    const float4 r4 = avg4(uh[base + j],       ut[base + j]);
    const float4 z4 = avg4(uh[base + 75 + j],  ut[base + 75 + j]);
    const float4 n4 = avg4(uh[base + 150 + j], ut[base + 150 + j]);
    const float4 bb = ((const float4*)(bh + 600))[j];

    float4 o;
    { float r = 1.f/(1.f+expf(-r4.x)), z = 1.f/(1.f+expf(-z4.x)); o.x = (1.f-z)*tanhf(n4.x + r*bb.x); }
    { float r = 1.f/(1.f+expf(-r4.y)), z = 1.f/(1.f+expf(-z4.y)); o.y = (1.f-z)*tanhf(n4.y + r*bb.y); }
    { float r = 1.f/(1.f+expf(-r4.z)), z = 1.f/(1.f+expf(-z4.z)); o.z = (1.f-z)*tanhf(n4.z + r*bb.z); }
    { float r = 1.f/(1.f+expf(-r4.w)), z = 1.f/(1.f+expf(-z4.w)); o.w = (1.f-z)*tanhf(n4.w + r*bb.w); }
    out[grp * 75 + j] = o;
}

// ---------------- softmax over t per (b,l), then alpha[b,t] = sum_l ----------------
__global__ void __launch_bounds__(512) softmax_alpha_kernel()
{
    const int b = blockIdx.x;
    const float* S = g_scores + (size_t)b * NLQ * NT;
    __shared__ float rmax[NLQ];
    __shared__ float rinv[NLQ];

    const int tid = threadIdx.x;
    const int wid = tid >> 5, lane = tid & 31;

    for (int l = wid; l < NLQ; l += 16) {
        const float* row = S + (size_t)l * NT;
        float v[16], m = -1e30f;
#pragma unroll
        for (int q = 0; q < 16; ++q) { v[q] = row[lane + 32 * q]; m = fmaxf(m, v[q]); }
#pragma unroll
        for (int o = 16; o; o >>= 1) m = fmaxf(m, __shfl_xor_sync(0xffffffffu, m, o));
        float s = 0.f;
#pragma unroll
        for (int q = 0; q < 16; ++q) s += expf(v[q] - m);
#pragma unroll
        for (int o = 16; o; o >>= 1) s += __shfl_xor_sync(0xffffffffu, s, o);
        if (lane == 0) { rmax[l] = m; rinv[l] = 1.f / s; }
    }
    __syncthreads();

    float acc = 0.f;
    const int t = tid;
    for (int l = 0; l < NLQ; ++l)
        acc += expf(S[(size_t)l * NT + t] - rmax[l]) * rinv[l];
    g_alpha[b * NT + t] = acc;
}

// ---------------- rep = alpha @ hid_ ; layernorm ----------------
__global__ void __launch_bounds__(320) rep_ln_kernel(const float* __restrict__ gamma,
                                                     const float* __restrict__ beta,
                                                     float* __restrict__ out)
{
    const int b = blockIdx.x;
    __shared__ float sal[NT];
    __shared__ float red[2][10];
    const int tid = threadIdx.x;

    for (int t = tid; t < NT; t += 320) sal[t] = g_alpha[b * NT + t];
    __syncthreads();

    float acc = 0.f;
    const float* H = g_hid + (size_t)b * NT * D_HID;
    if (tid < D_HID) {
        for (int t = 0; t < NT; ++t)
            acc = fmaf(sal[t], H[(size_t)t * D_HID + tid], acc);
    }
    float v1 = (tid < D_HID) ? acc : 0.f;
    float v2 = (tid < D_HID) ? acc * acc : 0.f;
#pragma unroll
    for (int o = 16; o; o >>= 1) {
        v1 += __shfl_xor_sync(0xffffffffu, v1, o);
        v2 += __shfl_xor_sync(0xffffffffu, v2, o);
    }
    const int wid = tid >> 5, lane = tid & 31;
    if (lane == 0) { red[0][wid] = v1; red[1][wid] = v2; }
    __syncthreads();
    if (tid == 0) {
        float s1 = 0.f, s2 = 0.f;
        for (int w = 0; w < 10; ++w) { s1 += red[0][w]; s2 += red[1][w]; }
        red[0][0] = s1 / (float)D_HID;
        red[1][0] = s2 / (float)D_HID;
    }
    __syncthreads();
    if (tid < D_HID) {
        float mu = red[0][0];
        float var = red[1][0] - mu * mu;
        out[b * D_HID + tid] = (acc - mu) * rsqrtf(var + 1e-5f) * gamma[tid] + beta[tid];
    }
}

__global__ void zero_tail_kernel(float* __restrict__ out, long start, long end)
{
    long i = start + (long)blockIdx.x * blockDim.x + threadIdx.x;
    if (i < end) out[i] = 0.f;
}

// ---------------- launch ----------------
extern "C" void kernel_launch(void* const* d_in, const int* in_sizes, int n_in,
                              void* d_out, int out_size)
{
    const int o = (in_sizes[3] == 1) ? 1 : 0;

    const float* nodes  = (const float*)d_in[0];
    const float* ctx    = (const float*)d_in[1];
    const int*   tri    = (const int*)d_in[2];
    const float* W_mean = (const float*)d_in[3 + o];
    const float* b_mean = (const float*)d_in[4 + o];
    const float* W_ih_f = (const float*)d_in[5 + o];
    const float* b_ih_f = (const float*)d_in[6 + o];
    const float* b_hh_f = (const float*)d_in[7 + o];
    const float* W_ih_b = (const float*)d_in[8 + o];
    const float* b_ih_b = (const float*)d_in[9 + o];
    const float* b_hh_b = (const float*)d_in[10 + o];
    const float* W_out  = (const float*)d_in[11 + o];
    const float* b_out  = (const float*)d_in[12 + o];
    const float* W_node = (const float*)d_in[13 + o];
    const float* b_node = (const float*)d_in[14 + o];
    const float* gamma  = (const float*)d_in[15 + o];
    const float* beta   = (const float*)d_in[16 + o];
    float* out = (float*)d_out;

    float *pWc, *pC, *pU, *pHidden, *pHid, *pScores;
    cudaGetSymbolAddress((void**)&pWc,     g_Wc);
    cudaGetSymbolAddress((void**)&pC,      g_c);
    cudaGetSymbolAddress((void**)&pU,      g_U);
    cudaGetSymbolAddress((void**)&pHidden, g_hidden);
    cudaGetSymbolAddress((void**)&pHid,    g_hid);
    cudaGetSymbolAddress((void**)&pScores, g_scores);

    cudaFuncSetAttribute(gemm_tf32_mma, cudaFuncAttributeMaxDynamicSharedMemorySize, GEMM_SMEM_BYTES);

    // 1. combined weights/biases
    combine_kernel<<<1800, 128>>>(W_ih_f, b_ih_f, b_hh_f, W_ih_b, b_ih_b, b_hh_b, W_mean, b_mean);

    // 2. U[32768,1800] = nodes @ Wc^T + c
    {
        dim3 grid((1800 + BN - 1) / BN, ROWS_BN / BM, 1);
        gemm_tf32_mma<<<grid, 256, GEMM_SMEM_BYTES>>>(nodes, 0, pWc, 0, pU, 0,
                                                      ROWS_BN, 1800, D_NODE, pC, 0);
    }
    // 3. node_feature[32768,300] = nodes @ W_node^T + b_node
    {
        dim3 grid((D_HID + BN - 1) / BN, ROWS_BN / BM, 1);
        gemm_tf32_mma<<<grid, 256, GEMM_SMEM_BYTES>>>(nodes, 0, W_node, 0, out + OUT_PATH, 0,
                                                      ROWS_BN, D_HID, D_NODE, b_node, 0);
    }
    // 4. GRU gates -> hidden[65536,600]
    gates_kernel<<<ROWS_BT, 160>>>(tri, b_hh_f, b_hh_b);

    // 5. hid_[65536,300] = tanh(hidden @ W_out^T + b_out)
    {
        dim3 grid((D_HID + BN - 1) / BN, ROWS_BT / BM, 1);
        gemm_tf32_mma<<<grid, 256, GEMM_SMEM_BYTES>>>(pHidden, 0, W_out, 0, pHid, 0,
                                                      ROWS_BT, D_HID, 600, b_out, 1);
    }
    // 6. scores[b,256,512] = ctx[b] @ hid_[b]^T
    {
        dim3 grid(NT / BN, NLQ / BM, NB);
        gemm_tf32_mma<<<grid, 256, GEMM_SMEM_BYTES>>>(ctx, (long)NLQ * D_HID,
                                                      pHid, (long)NT * D_HID,
                                                      pScores, (long)NLQ * NT,
                                                      NLQ, NT, D_HID, nullptr, 0);
    }
    // 7. softmax/alpha
    softmax_alpha_kernel<<<NB, 512>>>();
    // 8. rep + layernorm
    rep_ln_kernel<<<NB, 320>>>(gamma, beta, out);
    // 9. node_mask zeros
    {
        long start = OUT_TAIL_START;
        long end = (long)out_size;
        if (end > start) {
            long n = end - start;
            int blocks = (int)((n + 255) / 256);
            zero_tail_kernel<<<blocks, 256>>>(out, start, end);
        }
    }
}

// round 4
// speedup vs baseline: 2.7532x; 1.0204x over previous
#include <cuda_runtime.h>
#include <cuda_fp16.h>
#include <math.h>
#include <stdint.h>

// ---------------- problem constants ----------------
#define D_NODE 100
#define D_HID  300
#define NB     128
#define NT     512
#define NNODE  256
#define NLQ    256
#define ROWS_BT (NB*NT)     // 65536
#define ROWS_BN (NB*NNODE)  // 32768

#define OUT_PATH   (NB*D_HID)
#define OUT_NODEF  ((long)ROWS_BN*D_HID)
#define OUT_TAIL_START (OUT_PATH + OUT_NODEF)

// ---------------- device scratch ----------------
__device__ float  g_Wc[1800 * D_NODE];
__device__ float  g_c[1800];
__device__ float  g_U[(size_t)ROWS_BN * 1800];
__device__ __half g_hidden_h[(size_t)ROWS_BT * 600];   // fp16 GRU outputs
__device__ float  g_hid[(size_t)ROWS_BT * D_HID];
__device__ float  g_scores[(size_t)NB * NLQ * NT];
__device__ float  g_alpha[NB * NT];

// ---------------- PTX helpers (plain sm_10x — no arch-gated features) ----------------
__device__ __forceinline__ uint32_t smem_to_u32(const void* p) {
    uint32_t a;
    asm("{ .reg .u64 t; cvta.to.shared.u64 t, %1; cvt.u32.u64 %0, t; }" : "=r"(a) : "l"(p));
    return a;
}
__device__ __forceinline__ uint32_t f2tf32(float f) {
    uint32_t u;
    asm("cvt.rna.tf32.f32 %0, %1;" : "=r"(u) : "f"(f));
    return u;
}
__device__ __forceinline__ void mma_tf32(float* d, const uint32_t* a, const uint32_t* b) {
    asm volatile(
        "mma.sync.aligned.m16n8k8.row.col.f32.tf32.tf32.f32 "
        "{%0,%1,%2,%3}, {%4,%5,%6,%7}, {%8,%9}, {%0,%1,%2,%3};"
        : "+f"(d[0]), "+f"(d[1]), "+f"(d[2]), "+f"(d[3])
        : "r"(a[0]), "r"(a[1]), "r"(a[2]), "r"(a[3]), "r"(b[0]), "r"(b[1]));
}
__device__ __forceinline__ void cp_async16(uint32_t dst, const void* src, int src_size) {
    asm volatile("cp.async.cg.shared.global [%0], [%1], 16, %2;"
        :: "r"(dst), "l"(src), "r"(src_size) : "memory");
}
#define CP_COMMIT() asm volatile("cp.async.commit_group;" ::: "memory")
#define CP_WAIT(n)  asm volatile("cp.async.wait_group %0;" :: "n"(n) : "memory")

__device__ __forceinline__ float fexp2(float x) {
    float y; asm("ex2.approx.f32 %0, %1;" : "=f"(y) : "f"(x)); return y;
}
__device__ __forceinline__ float frcp(float x) {
    float y; asm("rcp.approx.f32 %0, %1;" : "=f"(y) : "f"(x)); return y;
}
#define LOG2E 1.4426950408889634f
__device__ __forceinline__ float fsigmoid(float x) { return frcp(1.f + fexp2(-LOG2E * x)); }
__device__ __forceinline__ float ftanh(float x)    { return 2.f * frcp(1.f + fexp2(-2.f * LOG2E * x)) - 1.f; }

// ================= tf32 mma.sync GEMM (A fp32 or fp16) =================
// C[m,n] = act( sum_k A[m,k]*W[n,k] + bias[n] ). A:[M,K] rm, W:[N,K] rm, C:[M,N] rm.
// M % 128 == 0; K % 8 == 0 (half A) / % 4 (float A); N even.
#define BM 128
#define BN 128

template <typename TA>
__global__ void __launch_bounds__(256, 2)
gemm_tf32_mma(const TA* __restrict__ A, long aBatch,
              const float* __restrict__ W, long wBatch,
              float* __restrict__ C, long cBatch,
              int M, int N, int K,
              const float* __restrict__ bias, int act_tanh)
{
    constexpr bool HALF_A = (sizeof(TA) == 2);
    constexpr int A_TILE_BYTES = HALF_A ? 128 * 40 * 2 : 128 * 36 * 4;
    constexpr int B_TILE_BYTES = 128 * 36 * 4;

    extern __shared__ char smc[];
    const uint32_t sm32 = smem_to_u32(smc);

    const int bz = blockIdx.z;
    A += (long)bz * aBatch; W += (long)bz * wBatch; C += (long)bz * cBatch;

    const int tid  = threadIdx.x;
    const int warp = tid >> 5, lane = tid & 31;
    const int wm = warp & 3, wn = warp >> 2;      // 4 x 2 warp grid
    const int g = lane >> 2, t = lane & 3;

    const int m0 = blockIdx.y * BM;
    const int n0 = blockIdx.x * BN;
    const int CH = (K + 31) >> 5;

    float acc[2][8][4];
#pragma unroll
    for (int i = 0; i < 2; ++i)
#pragma unroll
        for (int j = 0; j < 8; ++j)
#pragma unroll
            for (int q = 0; q < 4; ++q) acc[i][j][q] = 0.f;

    auto issue = [&](int c) {
        const int s = c & 1;
        const int kb = c << 5;
        const uint32_t aB = sm32 + s * A_TILE_BYTES;
        const uint32_t bB = sm32 + 2 * A_TILE_BYTES + s * B_TILE_BYTES;
        if constexpr (HALF_A) {
#pragma unroll
            for (int i = 0; i < 2; ++i) {
                const int seg = tid + i * 256;          // 0..511
                const int row = seg >> 2, q = seg & 3;
                const int k = kb + q * 8;
                const int va = (k + 8 <= K);
                cp_async16(aB + (uint32_t)(row * 80 + q * 16),
                           va ? (const void*)(A + (long)(m0 + row) * K + k) : (const void*)A,
                           va ? 16 : 0);
            }
        } else {
#pragma unroll
            for (int i = 0; i < 4; ++i) {
                const int seg = tid + i * 256;          // 0..1023
                const int row = seg >> 3, q = seg & 7;
                const int k = kb + q * 4;
                const int va = (k + 4 <= K);
                cp_async16(aB + (uint32_t)(row * 144 + q * 16),
                           va ? (const void*)(A + (long)(m0 + row) * K + k) : (const void*)A,
                           va ? 16 : 0);
            }
        }
#pragma unroll
        for (int i = 0; i < 4; ++i) {
            const int seg = tid + i * 256;
            const int row = seg >> 3, q = seg & 7;
            const int k = kb + q * 4;
            const int vb = (k + 4 <= K) && (n0 + row < N);
            cp_async16(bB + (uint32_t)(row * 144 + q * 16),
                       vb ? (const void*)(W + (long)(n0 + row) * K + k) : (const void*)W,
                       vb ? 16 : 0);
        }
        CP_COMMIT();
    };

    issue(0);
    for (int c = 0; c < CH; ++c) {
        if (c + 1 < CH) { issue(c + 1); CP_WAIT(1); }
        else            { CP_WAIT(0); }
        __syncthreads();

        const char* aBuf = smc + (c & 1) * A_TILE_BYTES;
        const float* b_ = (const float*)(smc + 2 * A_TILE_BYTES + (c & 1) * B_TILE_BYTES);

#pragma unroll
        for (int kk = 0; kk < 4; ++kk) {
            const int col = kk * 8 + t;
            uint32_t af[2][4], bf[8][2];
            if constexpr (HALF_A) {
                const __half* a_ = (const __half*)aBuf;
#pragma unroll
                for (int tm = 0; tm < 2; ++tm) {
                    const int r = wm * 32 + tm * 16 + g;
                    af[tm][0] = f2tf32(__half2float(a_[r * 40 + col]));
                    af[tm][1] = f2tf32(__half2float(a_[(r + 8) * 40 + col]));
                    af[tm][2] = f2tf32(__half2float(a_[r * 40 + col + 4]));
                    af[tm][3] = f2tf32(__half2float(a_[(r + 8) * 40 + col + 4]));
                }
            } else {
                const float* a_ = (const float*)aBuf;
#pragma unroll
                for (int tm = 0; tm < 2; ++tm) {
                    const int r = wm * 32 + tm * 16 + g;
                    af[tm][0] = f2tf32(a_[r * 36 + col]);
                    af[tm][1] = f2tf32(a_[(r + 8) * 36 + col]);
                    af[tm][2] = f2tf32(a_[r * 36 + col + 4]);
                    af[tm][3] = f2tf32(a_[(r + 8) * 36 + col + 4]);
                }
            }
#pragma unroll
            for (int tn = 0; tn < 8; ++tn) {
                const int n = wn * 64 + tn * 8 + g;
                bf[tn][0] = f2tf32(b_[n * 36 + col]);
                bf[tn][1] = f2tf32(b_[n * 36 + col + 4]);
            }
#pragma unroll
            for (int tm = 0; tm < 2; ++tm)
#pragma unroll
                for (int tn = 0; tn < 8; ++tn)
                    mma_tf32(acc[tm][tn], af[tm], bf[tn]);
        }
        __syncthreads();
    }

#pragma unroll
    for (int tm = 0; tm < 2; ++tm) {
        const int row = m0 + wm * 32 + tm * 16 + g;
#pragma unroll
        for (int tn = 0; tn < 8; ++tn) {
            const int n = n0 + wn * 64 + tn * 8 + 2 * t;
            if (n < N) {
                float b0 = 0.f, b1 = 0.f;
                if (bias) { b0 = bias[n]; b1 = bias[n + 1]; }
                float v0 = acc[tm][tn][0] + b0;
                float v1 = acc[tm][tn][1] + b1;
                float v2 = acc[tm][tn][2] + b0;
                float v3 = acc[tm][tn][3] + b1;
                if (act_tanh) { v0 = ftanh(v0); v1 = ftanh(v1); v2 = ftanh(v2); v3 = ftanh(v3); }
                *(float2*)(C + (long)row * N + n)       = make_float2(v0, v1);
                *(float2*)(C + (long)(row + 8) * N + n) = make_float2(v2, v3);
            }
        }
    }
}

#define GEMM_SMEM_F ((2 * 128 * 36 * 4) + (2 * 128 * 36 * 4))   // 73728
#define GEMM_SMEM_H ((2 * 128 * 40 * 2) + (2 * 128 * 36 * 4))   // 57344

// ---------------- weight combine (tiled, Wmean staged in smem) ----------------
#define CBJ 16
#define COMBINE_SMEM ((30000 + CBJ * 300) * 4)   // 139200 B

__global__ void __launch_bounds__(256)
combine_kernel(const float* __restrict__ Wf, const float* __restrict__ bif,
               const float* __restrict__ bhf,
               const float* __restrict__ Wb, const float* __restrict__ bib,
               const float* __restrict__ bhb,
               const float* __restrict__ Wmean, const float* __restrict__ bmean)
{
    extern __shared__ float csm[];
    float* sW   = csm;            // [300*100]
    float* srow = csm + 30000;    // [CBJ][300]

    const int j0 = blockIdx.x * CBJ;
    const int tid = threadIdx.x;

    for (int i = tid; i < 30000; i += 256) sW[i] = Wmean[i];
    for (int i = tid; i < CBJ * 300; i += 256) {
        const int jj = i / 300, d = i % 300, j = j0 + jj;
        float v = 0.f;
        if (j < 1800) v = (j < 900) ? Wf[j * 300 + d] : Wb[(j - 900) * 300 + d];
        srow[i] = v;
    }
    __syncthreads();

    for (int idx = tid; idx < CBJ * 100; idx += 256) {
        const int jj = idx / 100, k = idx % 100, j = j0 + jj;
        if (j >= 1800) continue;
        const float* wr = srow + jj * 300;
        float s = 0.f;
#pragma unroll 4
        for (int d = 0; d < 300; ++d) s = fmaf(wr[d], sW[d * 100 + k], s);
        g_Wc[j * 100 + k] = s;
    }
    if (tid < CBJ) {
        const int j = j0 + tid;
        if (j < 1800) {
            const int fwd = (j < 900), jj2 = fwd ? j : j - 900;
            const float* bih = fwd ? bif : bib;
            const float* bhh = fwd ? bhf : bhb;
            const float* wr = srow + tid * 300;
            float s = bih[jj2];
            for (int d = 0; d < 300; ++d) s = fmaf(wr[d], bmean[d], s);
            if (jj2 < 600) s += bhh[jj2];
            g_c[j] = s;
        }
    }
}

// ---------------- GRU gates (fast math, fp16 output) ----------------
__device__ __forceinline__ float4 avg4(float4 a, float4 b) {
    return make_float4(0.5f * (a.x + b.x), 0.5f * (a.y + b.y),
                       0.5f * (a.z + b.z), 0.5f * (a.w + b.w));
}
__global__ void __launch_bounds__(160) gates_kernel(const int* __restrict__ tri,
                                                    const float* __restrict__ bhf,
                                                    const float* __restrict__ bhb)
{
    const int bt = blockIdx.x;
    const int b = bt >> 9;
    const int h = tri[bt * 3 + 0];
    const int t = tri[bt * 3 + 2];
    const float4* uh = (const float4*)(g_U + (size_t)(b * NNODE + h) * 1800);
    const float4* ut = (const float4*)(g_U + (size_t)(b * NNODE + t) * 1800);
    uint2* out = (uint2*)(g_hidden_h + (size_t)bt * 600);

    const int tid = threadIdx.x;
    int grp, j;
    if (tid < 75)                    { grp = 0; j = tid; }
    else if (tid >= 80 && tid < 155) { grp = 1; j = tid - 80; }
    else return;

    const int base = grp * 225;
    const float* bh = grp ? bhb : bhf;
    const float4 r4 = avg4(uh[base + j],       ut[base + j]);
    const float4 z4 = avg4(uh[base + 75 + j],  ut[base + 75 + j]);
    const float4 n4 = avg4(uh[base + 150 + j], ut[base + 150 + j]);
    const float4 bb = ((const float4*)(bh + 600))[j];

    float4 o;
    o.x = (1.f - fsigmoid(z4.x)) * ftanh(n4.x + fsigmoid(r4.x) * bb.x);
    o.y = (1.f - fsigmoid(z4.y)) * ftanh(n4.y + fsigmoid(r4.y) * bb.y);
    o.z = (1.f - fsigmoid(z4.z)) * ftanh(n4.z + fsigmoid(r4.z) * bb.z);
    o.w = (1.f - fsigmoid(z4.w)) * ftanh(n4.w + fsigmoid(r4.w) * bb.w);

    __half2 h0 = __floats2half2_rn(o.x, o.y);
    __half2 h1 = __floats2half2_rn(o.z, o.w);
    uint2 v;
    v.x = *reinterpret_cast<uint32_t*>(&h0);
    v.y = *reinterpret_cast<uint32_t*>(&h1);
    out[grp * 75 + j] = v;
}

// ---------------- single-pass softmax over t per (b,l) + alpha[b,t] = sum_l ----------------
__global__ void __launch_bounds__(512) softmax_alpha_kernel()
{
    const int b = blockIdx.x;
    const float* S = g_scores + (size_t)b * NLQ * NT;
    __shared__ float part[16][NT];     // per-warp partial alpha, 32 KB

    const int tid = threadIdx.x;
    const int w = tid >> 5, lane = tid & 31;

    float pacc[16];
#pragma unroll
    for (int q = 0; q < 16; ++q) pacc[q] = 0.f;

    for (int l = w; l < NLQ; l += 16) {
        const float* row = S + (size_t)l * NT;
        float v[16], m = -1e30f;
#pragma unroll
        for (int q = 0; q < 16; ++q) { v[q] = row[lane + 32 * q]; m = fmaxf(m, v[q]); }
#pragma unroll
        for (int o = 16; o; o >>= 1) m = fmaxf(m, __shfl_xor_sync(0xffffffffu, m, o));
        float e[16], s = 0.f;
#pragma unroll
        for (int q = 0; q < 16; ++q) { e[q] = fexp2(LOG2E * (v[q] - m)); s += e[q]; }
#pragma unroll
        for (int o = 16; o; o >>= 1) s += __shfl_xor_sync(0xffffffffu, s, o);
        const float rinv = frcp(s);
#pragma unroll
        for (int q = 0; q < 16; ++q) pacc[q] += e[q] * rinv;
    }
#pragma unroll
    for (int q = 0; q < 16; ++q) part[w][lane + 32 * q] = pacc[q];
    __syncthreads();

    float s = 0.f;
#pragma unroll
    for (int w2 = 0; w2 < 16; ++w2) s += part[w2][tid];
    g_alpha[b * NT + tid] = s;
}

// ---------------- rep = alpha @ hid_ ; layernorm ----------------
__global__ void __launch_bounds__(320) rep_ln_kernel(const float* __restrict__ gamma,
                                                     const float* __restrict__ beta,
                                                     float* __restrict__ out)
{
    const int b = blockIdx.x;
    __shared__ float sal[NT];
    __shared__ float red[2][10];
    const int tid = threadIdx.x;

    for (int t = tid; t < NT; t += 320) sal[t] = g_alpha[b * NT + t];
    __syncthreads();

    float acc = 0.f;
    const float* H = g_hid + (size_t)b * NT * D_HID;
    if (tid < D_HID) {
        for (int t = 0; t < NT; ++t)
            acc = fmaf(sal[t], H[(size_t)t * D_HID + tid], acc);
    }
    float v1 = (tid < D_HID) ? acc : 0.f;
    float v2 = (tid < D_HID) ? acc * acc : 0.f;
#pragma unroll
    for (int o = 16; o; o >>= 1) {
        v1 += __shfl_xor_sync(0xffffffffu, v1, o);
        v2 += __shfl_xor_sync(0xffffffffu, v2, o);
    }
    const int wid = tid >> 5, lane = tid & 31;
    if (lane == 0) { red[0][wid] = v1; red[1][wid] = v2; }
    __syncthreads();
    if (tid == 0) {
        float s1 = 0.f, s2 = 0.f;
        for (int w = 0; w < 10; ++w) { s1 += red[0][w]; s2 += red[1][w]; }
        red[0][0] = s1 / (float)D_HID;
        red[1][0] = s2 / (float)D_HID;
    }
    __syncthreads();
    if (tid < D_HID) {
        float mu = red[0][0];
        float var = red[1][0] - mu * mu;
        out[b * D_HID + tid] = (acc - mu) * rsqrtf(var + 1e-5f) * gamma[tid] + beta[tid];
    }
}

__global__ void zero_tail_kernel(float* __restrict__ out, long start, long end)
{
    long i = start + (long)blockIdx.x * blockDim.x + threadIdx.x;
    if (i < end) out[i] = 0.f;
}

// ---------------- launch ----------------
extern "C" void kernel_launch(void* const* d_in, const int* in_sizes, int n_in,
                              void* d_out, int out_size)
{
    const int o = (in_sizes[3] == 1) ? 1 : 0;

    const float* nodes  = (const float*)d_in[0];
    const float* ctx    = (const float*)d_in[1];
    const int*   tri    = (const int*)d_in[2];
    const float* W_mean = (const float*)d_in[3 + o];
    const float* b_mean = (const float*)d_in[4 + o];
    const float* W_ih_f = (const float*)d_in[5 + o];
    const float* b_ih_f = (const float*)d_in[6 + o];
    const float* b_hh_f = (const float*)d_in[7 + o];
    const float* W_ih_b = (const float*)d_in[8 + o];
    const float* b_ih_b = (const float*)d_in[9 + o];
    const float* b_hh_b = (const float*)d_in[10 + o];
    const float* W_out  = (const float*)d_in[11 + o];
    const float* b_out  = (const float*)d_in[12 + o];
    const float* W_node = (const float*)d_in[13 + o];
    const float* b_node = (const float*)d_in[14 + o];
    const float* gamma  = (const float*)d_in[15 + o];
    const float* beta   = (const float*)d_in[16 + o];
    float* out = (float*)d_out;

    float *pWc, *pC, *pU, *pHid, *pScores;
    __half* pHiddenH;
    cudaGetSymbolAddress((void**)&pWc,      g_Wc);
    cudaGetSymbolAddress((void**)&pC,       g_c);
    cudaGetSymbolAddress((void**)&pU,       g_U);
    cudaGetSymbolAddress((void**)&pHiddenH, g_hidden_h);
    cudaGetSymbolAddress((void**)&pHid,     g_hid);
    cudaGetSymbolAddress((void**)&pScores,  g_scores);

    cudaFuncSetAttribute(gemm_tf32_mma<float>,  cudaFuncAttributeMaxDynamicSharedMemorySize, GEMM_SMEM_F);
    cudaFuncSetAttribute(gemm_tf32_mma<__half>, cudaFuncAttributeMaxDynamicSharedMemorySize, GEMM_SMEM_H);
    cudaFuncSetAttribute(combine_kernel,        cudaFuncAttributeMaxDynamicSharedMemorySize, COMBINE_SMEM);

    // 1. combined weights/biases
    combine_kernel<<<(1800 + CBJ - 1) / CBJ, 256, COMBINE_SMEM>>>(
        W_ih_f, b_ih_f, b_hh_f, W_ih_b, b_ih_b, b_hh_b, W_mean, b_mean);

    // 2. U[32768,1800] = nodes @ Wc^T + c
    {
        dim3 grid((1800 + BN - 1) / BN, ROWS_BN / BM, 1);
        gemm_tf32_mma<float><<<grid, 256, GEMM_SMEM_F>>>(nodes, 0, pWc, 0, pU, 0,
                                                         ROWS_BN, 1800, D_NODE, pC, 0);
    }
    // 3. node_feature[32768,300] = nodes @ W_node^T + b_node
    {
        dim3 grid((D_HID + BN - 1) / BN, ROWS_BN / BM, 1);
        gemm_tf32_mma<float><<<grid, 256, GEMM_SMEM_F>>>(nodes, 0, W_node, 0, out + OUT_PATH, 0,
                                                         ROWS_BN, D_HID, D_NODE, b_node, 0);
    }
    // 4. GRU gates -> hidden_h[65536,600] (fp16)
    gates_kernel<<<ROWS_BT, 160>>>(tri, b_hh_f, b_hh_b);

    // 5. hid_[65536,300] = tanh(hidden @ W_out^T + b_out)
    {
        dim3 grid((D_HID + BN - 1) / BN, ROWS_BT / BM, 1);
        gemm_tf32_mma<__half><<<grid, 256, GEMM_SMEM_H>>>(pHiddenH, 0, W_out, 0, pHid, 0,
                                                          ROWS_BT, D_HID, 600, b_out, 1);
    }
    // 6. scores[b,256,512] = ctx[b] @ hid_[b]^T
    {
        dim3 grid(NT / BN, NLQ / BM, NB);
        gemm_tf32_mma<float><<<grid, 256, GEMM_SMEM_F>>>(ctx, (long)NLQ * D_HID,
                                                         pHid, (long)NT * D_HID,
                                                         pScores, (long)NLQ * NT,
                                                         NLQ, NT, D_HID, nullptr, 0);
    }
    // 7. single-pass softmax/alpha
    softmax_alpha_kernel<<<NB, 512>>>();
    // 8. rep + layernorm
    rep_ln_kernel<<<NB, 320>>>(gamma, beta, out);
    // 9. node_mask zeros
    {
        long start = OUT_TAIL_START;
        long end = (long)out_size;
        if (end > start) {
            long n = end - start;
            int blocks = (int)((n + 255) / 256);
            zero_tail_kernel<<<blocks, 256>>>(out, start, end);
        }
    }
}

// round 5
// speedup vs baseline: 3.7521x; 1.3628x over previous
#include <cuda_runtime.h>
#include <cuda_fp16.h>
#include <math.h>
#include <stdint.h>

// ---------------- problem constants ----------------
#define D_NODE 100
#define D_HID  300
#define NB     128
#define NT     512
#define NNODE  256
#define NLQ    256
#define ROWS_BT (NB*NT)     // 65536
#define ROWS_BN (NB*NNODE)  // 32768

#define KN_PAD 112          // 100 -> 112 (14 x 8-half segments)
#define KH_PAD 304          // 300 -> 304 (38 segments)

#define OUT_PATH   (NB*D_HID)
#define OUT_NODEF  ((long)ROWS_BN*D_HID)
#define OUT_TAIL_START (OUT_PATH + OUT_NODEF)

// ---------------- device scratch ----------------
__device__ __half g_nodes_h[(size_t)ROWS_BN * KN_PAD];
__device__ __half g_ctx_h[(size_t)NB * NLQ * KH_PAD];
__device__ __half g_Wc_h[1800 * KN_PAD];
__device__ __half g_Wnode_h[300 * KN_PAD];
__device__ __half g_Wout_h[300 * 600];
__device__ float  g_c[1800];
__device__ __half g_U_h[(size_t)ROWS_BN * 1800];
__device__ __half g_hidden_h[(size_t)ROWS_BT * 600];
__device__ __half g_hid_h[(size_t)ROWS_BT * KH_PAD];
__device__ __half g_scores_h[(size_t)NB * NLQ * NT];
__device__ float  g_alpha[NB * NT];

// ---------------- PTX helpers ----------------
__device__ __forceinline__ uint32_t smem_to_u32(const void* p) {
    uint32_t a;
    asm("{ .reg .u64 t; cvta.to.shared.u64 t, %1; cvt.u32.u64 %0, t; }" : "=r"(a) : "l"(p));
    return a;
}
__device__ __forceinline__ void mma_f16(float* d, const uint32_t* a, const uint32_t* b) {
    asm volatile(
        "mma.sync.aligned.m16n8k16.row.col.f32.f16.f16.f32 "
        "{%0,%1,%2,%3}, {%4,%5,%6,%7}, {%8,%9}, {%0,%1,%2,%3};"
        : "+f"(d[0]), "+f"(d[1]), "+f"(d[2]), "+f"(d[3])
        : "r"(a[0]), "r"(a[1]), "r"(a[2]), "r"(a[3]), "r"(b[0]), "r"(b[1]));
}
__device__ __forceinline__ void cp_async16(uint32_t dst, const void* src, int src_size) {
    asm volatile("cp.async.cg.shared.global [%0], [%1], 16, %2;"
        :: "r"(dst), "l"(src), "r"(src_size) : "memory");
}
#define CP_COMMIT() asm volatile("cp.async.commit_group;" ::: "memory")
#define CP_WAIT(n)  asm volatile("cp.async.wait_group %0;" :: "n"(n) : "memory")

__device__ __forceinline__ float fexp2(float x) {
    float y; asm("ex2.approx.f32 %0, %1;" : "=f"(y) : "f"(x)); return y;
}
__device__ __forceinline__ float frcp(float x) {
    float y; asm("rcp.approx.f32 %0, %1;" : "=f"(y) : "f"(x)); return y;
}
#define LOG2E 1.4426950408889634f
__device__ __forceinline__ float fsigmoid(float x) { return frcp(1.f + fexp2(-LOG2E * x)); }
__device__ __forceinline__ float ftanh(float x)    { return 2.f * frcp(1.f + fexp2(-2.f * LOG2E * x)) - 1.f; }

// ================= fp16 mma.sync GEMM =================
// C[m,n] = act( sum_k A[m,k]*W[n,k] + bias[n] ). A:[M,K] rm fp16, W:[N,K] rm fp16.
// K multiple of 8 (padded, pad zeroed). M % 128 == 0. N even.
// OUT_HALF: C is fp16 with row stride Npad (cols [N,Npad) zero-filled); else fp32, stride N.
#define BM 128
#define BN 128
#define ASTR 40                                 // smem row stride in halves

template <bool OUT_HALF>
__global__ void __launch_bounds__(256, 2)
gemm_f16(const __half* __restrict__ A, long aBatch,
         const __half* __restrict__ W, long wBatch,
         void* __restrict__ Cv, long cBatch,
         int M, int N, int Npad, int K,
         const float* __restrict__ bias, int act_tanh)
{
    __shared__ __half sA[2][BM * ASTR];
    __shared__ __half sB[2][BN * ASTR];

    const int bz = blockIdx.z;
    A += (long)bz * aBatch; W += (long)bz * wBatch;

    const int tid  = threadIdx.x;
    const int warp = tid >> 5, lane = tid & 31;
    const int wm = warp & 3, wn = warp >> 2;     // 4 x 2 warp grid
    const int g = lane >> 2, t = lane & 3;

    const int m0 = blockIdx.y * BM;
    const int n0 = blockIdx.x * BN;
    const int CH = (K + 31) >> 5;

    const uint32_t sA32 = smem_to_u32(sA);
    const uint32_t sB32 = smem_to_u32(sB);

    float acc[2][8][4];
#pragma unroll
    for (int i = 0; i < 2; ++i)
#pragma unroll
        for (int j = 0; j < 8; ++j)
#pragma unroll
            for (int q = 0; q < 4; ++q) acc[i][j][q] = 0.f;

    auto issue = [&](int c) {
        const int s = c & 1;
        const int kb = c << 5;
        const uint32_t aB = sA32 + (uint32_t)s * (BM * ASTR * 2);
        const uint32_t bB = sB32 + (uint32_t)s * (BN * ASTR * 2);
        // 128 rows x 4 segments (16B = 8 halves) each, 256 threads -> 2 per tensor
#pragma unroll
        for (int i = 0; i < 2; ++i) {
            const int seg = tid + i * 256;       // 0..511
            const int row = seg >> 2, q = seg & 3;
            const int k = kb + q * 8;
            const int va = (k + 8 <= K);
            cp_async16(aB + (uint32_t)(row * (ASTR * 2) + q * 16),
                       va ? (const void*)(A + (long)(m0 + row) * K + k) : (const void*)A,
                       va ? 16 : 0);
            const int vb = va && (n0 + row < N);
            cp_async16(bB + (uint32_t)(row * (ASTR * 2) + q * 16),
                       vb ? (const void*)(W + (long)(n0 + row) * K + k) : (const void*)W,
                       vb ? 16 : 0);
        }
        CP_COMMIT();
    };

    issue(0);
    for (int c = 0; c < CH; ++c) {
        if (c + 1 < CH) { issue(c + 1); CP_WAIT(1); }
        else            { CP_WAIT(0); }
        __syncthreads();

        const __half* a_ = sA[c & 1];
        const __half* b_ = sB[c & 1];

#pragma unroll
        for (int kk = 0; kk < 2; ++kk) {         // two k16 steps per 32-k chunk
            const int col = kk * 16 + 2 * t;
            uint32_t af[2][4], bf[8][2];
#pragma unroll
            for (int tm = 0; tm < 2; ++tm) {
                const int r = wm * 32 + tm * 16 + g;
                af[tm][0] = *(const uint32_t*)(a_ + r * ASTR + col);
                af[tm][1] = *(const uint32_t*)(a_ + (r + 8) * ASTR + col);
                af[tm][2] = *(const uint32_t*)(a_ + r * ASTR + col + 8);
                af[tm][3] = *(const uint32_t*)(a_ + (r + 8) * ASTR + col + 8);
            }
#pragma unroll
            for (int tn = 0; tn < 8; ++tn) {
                const int n = wn * 64 + tn * 8 + g;
                bf[tn][0] = *(const uint32_t*)(b_ + n * ASTR + col);
                bf[tn][1] = *(const uint32_t*)(b_ + n * ASTR + col + 8);
            }
#pragma unroll
            for (int tm = 0; tm < 2; ++tm)
#pragma unroll
                for (int tn = 0; tn < 8; ++tn)
                    mma_f16(acc[tm][tn], af[tm], bf[tn]);
        }
        __syncthreads();
    }

    // epilogue
#pragma unroll
    for (int tm = 0; tm < 2; ++tm) {
        const int row = m0 + wm * 32 + tm * 16 + g;
#pragma unroll
        for (int tn = 0; tn < 8; ++tn) {
            const int n = n0 + wn * 64 + tn * 8 + 2 * t;
            if (OUT_HALF ? (n < Npad) : (n < N)) {
                float v0 = 0.f, v1 = 0.f, v2 = 0.f, v3 = 0.f;
                if (n < N) {
                    float b0 = 0.f, b1 = 0.f;
                    if (bias) { b0 = bias[n]; b1 = bias[n + 1]; }
                    v0 = acc[tm][tn][0] + b0;
                    v1 = acc[tm][tn][1] + b1;
                    v2 = acc[tm][tn][2] + b0;
                    v3 = acc[tm][tn][3] + b1;
                    if (act_tanh) { v0 = ftanh(v0); v1 = ftanh(v1); v2 = ftanh(v2); v3 = ftanh(v3); }
                }
                if constexpr (OUT_HALF) {
                    __half* C = (__half*)Cv + (long)bz * cBatch;
                    *(__half2*)(C + (size_t)row * Npad + n)       = __floats2half2_rn(v0, v1);
                    *(__half2*)(C + (size_t)(row + 8) * Npad + n) = __floats2half2_rn(v2, v3);
                } else {
                    float* C = (float*)Cv + (long)bz * cBatch;
                    *(float2*)(C + (size_t)row * N + n)       = make_float2(v0, v1);
                    *(float2*)(C + (size_t)(row + 8) * N + n) = make_float2(v2, v3);
                }
            }
        }
    }
}

// ---------------- fp32 -> fp16 convert with row padding ----------------
__global__ void convert_pad(const float* __restrict__ src, __half* __restrict__ dst,
                            int rows, int K, int Kpad)
{
    const int total = rows * Kpad;
    for (int i = blockIdx.x * blockDim.x + threadIdx.x; i < total; i += gridDim.x * blockDim.x) {
        const int r = i / Kpad, k = i - r * Kpad;
        dst[i] = __float2half((k < K) ? src[(size_t)r * K + k] : 0.f);
    }
}

// ---------------- weight combine -> fp16 Wc (padded) + fp32 c ----------------
#define CBJ 16
#define COMBINE_SMEM ((30000 + CBJ * 300) * 4)

__global__ void __launch_bounds__(256)
combine_kernel(const float* __restrict__ Wf, const float* __restrict__ bif,
               const float* __restrict__ bhf,
               const float* __restrict__ Wb, const float* __restrict__ bib,
               const float* __restrict__ bhb,
               const float* __restrict__ Wmean, const float* __restrict__ bmean)
{
    extern __shared__ float csm[];
    float* sW   = csm;            // [300*100]
    float* srow = csm + 30000;    // [CBJ][300]

    const int j0 = blockIdx.x * CBJ;
    const int tid = threadIdx.x;

    for (int i = tid; i < 30000; i += 256) sW[i] = Wmean[i];
    for (int i = tid; i < CBJ * 300; i += 256) {
        const int jj = i / 300, d = i % 300, j = j0 + jj;
        float v = 0.f;
        if (j < 1800) v = (j < 900) ? Wf[j * 300 + d] : Wb[(j - 900) * 300 + d];
        srow[i] = v;
    }
    __syncthreads();

    for (int idx = tid; idx < CBJ * KN_PAD; idx += 256) {
        const int jj = idx / KN_PAD, k = idx % KN_PAD, j = j0 + jj;
        if (j >= 1800) continue;
        float s = 0.f;
        if (k < 100) {
            const float* wr = srow + jj * 300;
#pragma unroll 4
            for (int d = 0; d < 300; ++d) s = fmaf(wr[d], sW[d * 100 + k], s);
        }
        g_Wc_h[j * KN_PAD + k] = __float2half(s);
    }
    if (tid < CBJ) {
        const int j = j0 + tid;
        if (j < 1800) {
            const int fwd = (j < 900), jj2 = fwd ? j : j - 900;
            const float* bih = fwd ? bif : bib;
            const float* bhh = fwd ? bhf : bhb;
            const float* wr = srow + tid * 300;
            float s = bih[jj2];
            for (int d = 0; d < 300; ++d) s = fmaf(wr[d], bmean[d], s);
            if (jj2 < 600) s += bhh[jj2];
            g_c[j] = s;
        }
    }
}

// ---------------- GRU gates: read fp16 U, write fp16 hidden ----------------
__device__ __forceinline__ float4 h4_to_f4(const __half* p) {
    uint2 v = *(const uint2*)p;
    __half2 h0 = *reinterpret_cast<__half2*>(&v.x);
    __half2 h1 = *reinterpret_cast<__half2*>(&v.y);
    float2 f0 = __half22float2(h0), f1 = __half22float2(h1);
    return make_float4(f0.x, f0.y, f1.x, f1.y);
}
__device__ __forceinline__ float4 avg4(float4 a, float4 b) {
    return make_float4(0.5f * (a.x + b.x), 0.5f * (a.y + b.y),
                       0.5f * (a.z + b.z), 0.5f * (a.w + b.w));
}
__global__ void __launch_bounds__(160) gates_kernel(const int* __restrict__ tri,
                                                    const float* __restrict__ bhf,
                                                    const float* __restrict__ bhb)
{
    const int bt = blockIdx.x;
    const int b = bt >> 9;
    const int h = tri[bt * 3 + 0];
    const int t = tri[bt * 3 + 2];
    const __half* uh = g_U_h + (size_t)(b * NNODE + h) * 1800;
    const __half* ut = g_U_h + (size_t)(b * NNODE + t) * 1800;
    __half* out = g_hidden_h + (size_t)bt * 600;

    const int tid = threadIdx.x;
    int grp, j;
    if (tid < 75)                    { grp = 0; j = tid; }
    else if (tid >= 80 && tid < 155) { grp = 1; j = tid - 80; }
    else return;

    const int base = grp * 900 + 4 * j;          // half index
    const float* bh = grp ? bhb : bhf;
    const float4 r4 = avg4(h4_to_f4(uh + base),       h4_to_f4(ut + base));
    const float4 z4 = avg4(h4_to_f4(uh + base + 300), h4_to_f4(ut + base + 300));
    const float4 n4 = avg4(h4_to_f4(uh + base + 600), h4_to_f4(ut + base + 600));
    const float4 bb = ((const float4*)(bh + 600))[j];

    float4 o;
    o.x = (1.f - fsigmoid(z4.x)) * ftanh(n4.x + fsigmoid(r4.x) * bb.x);
    o.y = (1.f - fsigmoid(z4.y)) * ftanh(n4.y + fsigmoid(r4.y) * bb.y);
    o.z = (1.f - fsigmoid(z4.z)) * ftanh(n4.z + fsigmoid(r4.z) * bb.z);
    o.w = (1.f - fsigmoid(z4.w)) * ftanh(n4.w + fsigmoid(r4.w) * bb.w);

    __half2 h0 = __floats2half2_rn(o.x, o.y);
    __half2 h1 = __floats2half2_rn(o.z, o.w);
    uint2 v;
    v.x = *reinterpret_cast<uint32_t*>(&h0);
    v.y = *reinterpret_cast<uint32_t*>(&h1);
    *(uint2*)(out + grp * 300 + 4 * j) = v;
}

// ---------------- single-pass softmax over t per (b,l) + alpha[b,t] = sum_l ----------------
__global__ void __launch_bounds__(512) softmax_alpha_kernel()
{
    const int b = blockIdx.x;
    const __half* S = g_scores_h + (size_t)b * NLQ * NT;
    __shared__ float part[16][NT];               // 32 KB

    const int tid = threadIdx.x;
    const int w = tid >> 5, lane = tid & 31;

    float pacc[16];
#pragma unroll
    for (int q = 0; q < 16; ++q) pacc[q] = 0.f;

    for (int l = w; l < NLQ; l += 16) {
        const __half2* row2 = (const __half2*)(S + (size_t)l * NT);
        float v[16], m = -1e30f;
#pragma unroll
        for (int q = 0; q < 8; ++q) {
            float2 f = __half22float2(row2[lane + 32 * q]);
            v[2 * q] = f.x; v[2 * q + 1] = f.y;
            m = fmaxf(m, fmaxf(f.x, f.y));
        }
#pragma unroll
        for (int o = 16; o; o >>= 1) m = fmaxf(m, __shfl_xor_sync(0xffffffffu, m, o));
        float e[16], s = 0.f;
#pragma unroll
        for (int q = 0; q < 16; ++q) { e[q] = fexp2(LOG2E * (v[q] - m)); s += e[q]; }
#pragma unroll
        for (int o = 16; o; o >>= 1) s += __shfl_xor_sync(0xffffffffu, s, o);
        const float rinv = frcp(s);
#pragma unroll
        for (int q = 0; q < 16; ++q) pacc[q] += e[q] * rinv;
    }
#pragma unroll
    for (int q = 0; q < 8; ++q) {
        const int c = 2 * (lane + 32 * q);
        part[w][c]     = pacc[2 * q];
        part[w][c + 1] = pacc[2 * q + 1];
    }
    __syncthreads();

    float s = 0.f;
#pragma unroll
    for (int w2 = 0; w2 < 16; ++w2) s += part[w2][tid];
    g_alpha[b * NT + tid] = s;
}

// ---------------- rep = alpha @ hid_ ; layernorm ----------------
__global__ void __launch_bounds__(320) rep_ln_kernel(const float* __restrict__ gamma,
                                                     const float* __restrict__ beta,
                                                     float* __restrict__ out)
{
    const int b = blockIdx.x;
    __shared__ float sal[NT];
    __shared__ float red[2][10];
    const int tid = threadIdx.x;

    for (int t = tid; t < NT; t += 320) sal[t] = g_alpha[b * NT + t];
    __syncthreads();

    float acc = 0.f;
    const __half* H = g_hid_h + (size_t)b * NT * KH_PAD;
    if (tid < D_HID) {
        for (int t = 0; t < NT; ++t)
            acc = fmaf(sal[t], __half2float(H[(size_t)t * KH_PAD + tid]), acc);
    }
    float v1 = (tid < D_HID) ? acc : 0.f;
    float v2 = (tid < D_HID) ? acc * acc : 0.f;
#pragma unroll
    for (int o = 16; o; o >>= 1) {
        v1 += __shfl_xor_sync(0xffffffffu, v1, o);
        v2 += __shfl_xor_sync(0xffffffffu, v2, o);
    }
    const int wid = tid >> 5, lane = tid & 31;
    if (lane == 0) { red[0][wid] = v1; red[1][wid] = v2; }
    __syncthreads();
    if (tid == 0) {
        float s1 = 0.f, s2 = 0.f;
        for (int w = 0; w < 10; ++w) { s1 += red[0][w]; s2 += red[1][w]; }
        red[0][0] = s1 / (float)D_HID;
        red[1][0] = s2 / (float)D_HID;
    }
    __syncthreads();
    if (tid < D_HID) {
        float mu = red[0][0];
        float var = red[1][0] - mu * mu;
        out[b * D_HID + tid] = (acc - mu) * rsqrtf(var + 1e-5f) * gamma[tid] + beta[tid];
    }
}

__global__ void zero_tail_kernel(float* __restrict__ out, long start, long end)
{
    long i = start + (long)blockIdx.x * blockDim.x + threadIdx.x;
    if (i < end) out[i] = 0.f;
}

// ---------------- launch ----------------
extern "C" void kernel_launch(void* const* d_in, const int* in_sizes, int n_in,
                              void* d_out, int out_size)
{
    const int o = (in_sizes[3] == 1) ? 1 : 0;

    const float* nodes  = (const float*)d_in[0];
    const float* ctx    = (const float*)d_in[1];
    const int*   tri    = (const int*)d_in[2];
    const float* W_mean = (const float*)d_in[3 + o];
    const float* b_mean = (const float*)d_in[4 + o];
    const float* W_ih_f = (const float*)d_in[5 + o];
    const float* b_ih_f = (const float*)d_in[6 + o];
    const float* b_hh_f = (const float*)d_in[7 + o];
    const float* W_ih_b = (const float*)d_in[8 + o];
    const float* b_ih_b = (const float*)d_in[9 + o];
    const float* b_hh_b = (const float*)d_in[10 + o];
    const float* W_out  = (const float*)d_in[11 + o];
    const float* b_out  = (const float*)d_in[12 + o];
    const float* W_node = (const float*)d_in[13 + o];
    const float* b_node = (const float*)d_in[14 + o];
    const float* gamma  = (const float*)d_in[15 + o];
    const float* beta   = (const float*)d_in[16 + o];
    float* out = (float*)d_out;

    __half *pNodesH, *pCtxH, *pWcH, *pWnodeH, *pWoutH, *pUH, *pHiddenH, *pHidH, *pScoresH;
    float* pC;
    cudaGetSymbolAddress((void**)&pNodesH,  g_nodes_h);
    cudaGetSymbolAddress((void**)&pCtxH,    g_ctx_h);
    cudaGetSymbolAddress((void**)&pWcH,     g_Wc_h);
    cudaGetSymbolAddress((void**)&pWnodeH,  g_Wnode_h);
    cudaGetSymbolAddress((void**)&pWoutH,   g_Wout_h);
    cudaGetSymbolAddress((void**)&pC,       g_c);
    cudaGetSymbolAddress((void**)&pUH,      g_U_h);
    cudaGetSymbolAddress((void**)&pHiddenH, g_hidden_h);
    cudaGetSymbolAddress((void**)&pHidH,    g_hid_h);
    cudaGetSymbolAddress((void**)&pScoresH, g_scores_h);

    cudaFuncSetAttribute(combine_kernel, cudaFuncAttributeMaxDynamicSharedMemorySize, COMBINE_SMEM);

    // 0. fp16 conversions (padded)
    convert_pad<<<4096, 256>>>(nodes,  pNodesH, ROWS_BN, D_NODE, KN_PAD);
    convert_pad<<<8192, 256>>>(ctx,    pCtxH,   NB * NLQ, D_HID, KH_PAD);
    convert_pad<<<132,  256>>>(W_node, pWnodeH, D_HID, D_NODE, KN_PAD);
    convert_pad<<<704,  256>>>(W_out,  pWoutH,  D_HID, 600, 600);

    // 1. combined weights/biases
    combine_kernel<<<(1800 + CBJ - 1) / CBJ, 256, COMBINE_SMEM>>>(
        W_ih_f, b_ih_f, b_hh_f, W_ih_b, b_ih_b, b_hh_b, W_mean, b_mean);

    // 2. U[32768,1800] = nodes @ Wc^T + c   (fp16 out)
    {
        dim3 grid((1800 + BN - 1) / BN, ROWS_BN / BM, 1);
        gemm_f16<true><<<grid, 256>>>(pNodesH, 0, pWcH, 0, pUH, 0,
                                      ROWS_BN, 1800, 1800, KN_PAD, pC, 0);
    }
    // 3. node_feature[32768,300] = nodes @ W_node^T + b_node   (fp32 out, final)
    {
        dim3 grid((D_HID + BN - 1) / BN, ROWS_BN / BM, 1);
        gemm_f16<false><<<grid, 256>>>(pNodesH, 0, pWnodeH, 0, out + OUT_PATH, 0,
                                       ROWS_BN, D_HID, D_HID, KN_PAD, b_node, 0);
    }
    // 4. GRU gates -> hidden[65536,600] fp16
    gates_kernel<<<ROWS_BT, 160>>>(tri, b_hh_f, b_hh_b);

    // 5. hid_[65536,304] = tanh(hidden @ W_out^T + b_out)   (fp16 out, padded)
    {
        dim3 grid((KH_PAD + BN - 1) / BN, ROWS_BT / BM, 1);
        gemm_f16<true><<<grid, 256>>>(pHiddenH, 0, pWoutH, 0, pHidH, 0,
                                      ROWS_BT, D_HID, KH_PAD, 600, b_out, 1);
    }
    // 6. scores[b,256,512] = ctx[b] @ hid_[b]^T   (fp16 out)
    {
        dim3 grid(NT / BN, NLQ / BM, NB);
        gemm_f16<true><<<grid, 256>>>(pCtxH, (long)NLQ * KH_PAD,
                                      pHidH, (long)NT * KH_PAD,
                                      pScoresH, (long)NLQ * NT,
                                      NLQ, NT, NT, KH_PAD, nullptr, 0);
    }
    // 7. single-pass softmax/alpha
    softmax_alpha_kernel<<<NB, 512>>>();
    // 8. rep + layernorm
    rep_ln_kernel<<<NB, 320>>>(gamma, beta, out);
    // 9. node_mask zeros
    {
        long start = OUT_TAIL_START;
        long end = (long)out_size;
        if (end > start) {
            long n = end - start;
            int blocks = (int)((n + 255) / 256);
            zero_tail_kernel<<<blocks, 256>>>(out, start, end);
        }
    }
}